// round 3
// baseline (speedup 1.0000x reference)
#include <cuda_runtime.h>
#include <cuda_bf16.h>

#define N_NODES_MAX 100000
#define HIDDEN 128

// Scratch accumulator (allocation-free rule: static __device__ array).
__device__ float g_agg[(size_t)N_NODES_MAX * HIDDEN];

// ---------------------------------------------------------------------------
// Kernel 1: zero the accumulator (float4 stores)
// ---------------------------------------------------------------------------
__global__ void zero_kernel(int count4) {
    int i = blockIdx.x * blockDim.x + threadIdx.x;
    if (i < count4) {
        ((float4*)g_agg)[i] = make_float4(0.f, 0.f, 0.f, 0.f);
    }
}

// ---------------------------------------------------------------------------
// Kernel 2: edge scatter.  One warp per edge.
//   agg[src] += prob[e] * hidden[dst]      (128 floats = 32 lanes x float4)
// Uses vector float4 atomicAdd (sm_90+) -> RED.E.ADD.F32.128 in SASS,
// 4x fewer L2 atomic ops than scalar.
// ---------------------------------------------------------------------------
__global__ void scatter_kernel(const float* __restrict__ prob,
                               const float* __restrict__ hidden,
                               const int* __restrict__ ei,
                               int n_edges) {
    int gid  = blockIdx.x * blockDim.x + threadIdx.x;
    int e    = gid >> 5;
    int lane = gid & 31;
    if (e >= n_edges) return;

    int src = __ldg(&ei[e]);             // edge_index[0][e]
    int dst = __ldg(&ei[n_edges + e]);   // edge_index[1][e]
    float p = __ldg(&prob[e]);

    const float4* hrow = (const float4*)(hidden + (size_t)dst * HIDDEN);
    float4 v = __ldg(&hrow[lane]);
    v.x *= p; v.y *= p; v.z *= p; v.w *= p;

    float4* arow = (float4*)(g_agg + (size_t)src * HIDDEN);
    atomicAdd(&arow[lane], v);
}

// ---------------------------------------------------------------------------
// Kernel 3: out = agg @ W^T + b    (W: [128,128] row-major [out][in])
// Persistent blocks, 256 threads.  W transposed into padded smem once per
// block; 16-row tiles of agg staged in smem; each thread computes
// 2 rows x 4 cols = 8 accumulators.
// smem layout (dynamic): Ws[128*132] | As[16*128] | Bs[128]
// ---------------------------------------------------------------------------
#define MT 16
#define WPAD 132

__global__ void gemm_kernel(const float* __restrict__ W,
                            const float* __restrict__ bias,
                            float* __restrict__ out,
                            int n_rows) {
    extern __shared__ float smem[];
    float* Ws = smem;                       // 128 * 132
    float* As = Ws + 128 * WPAD;            // MT * 128
    float* Bs = As + MT * 128;              // 128

    // Load W transposed: Ws[k*WPAD + j] = W[j*128 + k]
    for (int i = threadIdx.x; i < 128 * 128; i += blockDim.x) {
        int j = i >> 7;
        int k = i & 127;
        Ws[k * WPAD + j] = __ldg(&W[i]);
    }
    if (threadIdx.x < 128) Bs[threadIdx.x] = __ldg(&bias[threadIdx.x]);
    __syncthreads();

    int tx = threadIdx.x & 31;   // col group: cols [4*tx, 4*tx+3]
    int ty = threadIdx.x >> 5;   // row group: rows ty and ty+8 within tile

    int n_tiles = (n_rows + MT - 1) / MT;

    for (int tile = blockIdx.x; tile < n_tiles; tile += gridDim.x) {
        int row0 = tile * MT;

        // Stage agg tile [MT x 128] into smem (float4)
        {
            const float4* src = (const float4*)(g_agg + (size_t)row0 * HIDDEN);
            float4* dstp = (float4*)As;
            int lim = MT * 32;  // float4 count for full tile
            for (int i = threadIdx.x; i < lim; i += blockDim.x) {
                int r = i >> 5;
                float4 v = (row0 + r < n_rows) ? src[i]
                                               : make_float4(0.f, 0.f, 0.f, 0.f);
                dstp[i] = v;
            }
        }
        __syncthreads();

        float acc00 = 0.f, acc01 = 0.f, acc02 = 0.f, acc03 = 0.f;
        float acc10 = 0.f, acc11 = 0.f, acc12 = 0.f, acc13 = 0.f;

        const float* a0p = As + ty * 128;
        const float* a1p = As + (ty + 8) * 128;

#pragma unroll 8
        for (int k = 0; k < 128; k++) {
            float a0 = a0p[k];              // broadcast within warp
            float a1 = a1p[k];
            float4 w = *(const float4*)&Ws[k * WPAD + tx * 4];  // conflict-free
            acc00 = fmaf(a0, w.x, acc00);
            acc01 = fmaf(a0, w.y, acc01);
            acc02 = fmaf(a0, w.z, acc02);
            acc03 = fmaf(a0, w.w, acc03);
            acc10 = fmaf(a1, w.x, acc10);
            acc11 = fmaf(a1, w.y, acc11);
            acc12 = fmaf(a1, w.z, acc12);
            acc13 = fmaf(a1, w.w, acc13);
        }

        int col = tx * 4;
        float4 bv = *(const float4*)&Bs[col];
        int r0 = row0 + ty;
        int r1 = row0 + ty + 8;
        if (r0 < n_rows) {
            float4 o = make_float4(acc00 + bv.x, acc01 + bv.y,
                                   acc02 + bv.z, acc03 + bv.w);
            *(float4*)&out[(size_t)r0 * HIDDEN + col] = o;
        }
        if (r1 < n_rows) {
            float4 o = make_float4(acc10 + bv.x, acc11 + bv.y,
                                   acc12 + bv.z, acc13 + bv.w);
            *(float4*)&out[(size_t)r1 * HIDDEN + col] = o;
        }
        __syncthreads();
    }
}

// ---------------------------------------------------------------------------
// Launch
// Inputs (metadata order): probabilities [E], hidden [N,128], edge_index [2,E]
//                          lin_w [128,128], lin_b [128]
// Output: [N, 128] fp32
// ---------------------------------------------------------------------------
extern "C" void kernel_launch(void* const* d_in, const int* in_sizes, int n_in,
                              void* d_out, int out_size) {
    const float* prob   = (const float*)d_in[0];
    const float* hidden = (const float*)d_in[1];
    const int*   ei     = (const int*)d_in[2];
    const float* lin_w  = (const float*)d_in[3];
    const float* lin_b  = (const float*)d_in[4];
    float* out = (float*)d_out;

    int n_edges = in_sizes[0];
    int n_rows  = in_sizes[1] / HIDDEN;

    // 1. zero accumulator
    {
        int count4 = n_rows * (HIDDEN / 4);
        int blocks = (count4 + 255) / 256;
        zero_kernel<<<blocks, 256>>>(count4);
    }

    // 2. edge scatter (warp per edge)
    {
        long long threads = (long long)n_edges * 32;
        int blocks = (int)((threads + 255) / 256);
        scatter_kernel<<<blocks, 256>>>(prob, hidden, ei, n_edges);
    }

    // 3. linear layer
    {
        int smem_bytes = (128 * WPAD + MT * 128 + 128) * sizeof(float);
        cudaFuncSetAttribute(gemm_kernel,
                             cudaFuncAttributeMaxDynamicSharedMemorySize,
                             smem_bytes);
        gemm_kernel<<<296, 256, smem_bytes>>>(lin_w, lin_b, out, n_rows);
    }
}

// round 4
// speedup vs baseline: 1.7265x; 1.7265x over previous
#include <cuda_runtime.h>
#include <cuda_bf16.h>

#define N_NODES_MAX 100000
#define N_EDGES_MAX 1600000
#define HIDDEN 128

// Scratch (allocation-free rule: static __device__ arrays).
__device__ float g_agg[(size_t)N_NODES_MAX * HIDDEN];      // 51.2 MB
__device__ int2  g_meta[N_EDGES_MAX];                      // sorted (dst, prob-bits)
__device__ int   g_hist[N_NODES_MAX];
__device__ int   g_starts[N_NODES_MAX];
__device__ int   g_cursor[N_NODES_MAX];
__device__ int   g_blocksum[256];

// ---------------------------------------------------------------------------
// K1: zero histogram
// ---------------------------------------------------------------------------
__global__ void zero_hist_kernel(int n) {
    int i = blockIdx.x * blockDim.x + threadIdx.x;
    if (i < n) g_hist[i] = 0;
}

// ---------------------------------------------------------------------------
// K2: histogram of src node ids
// ---------------------------------------------------------------------------
__global__ void hist_kernel(const int* __restrict__ ei, int n_edges) {
    int e = blockIdx.x * blockDim.x + threadIdx.x;
    if (e < n_edges) atomicAdd(&g_hist[__ldg(&ei[e])], 1);
}

// ---------------------------------------------------------------------------
// K3a/b/c: exclusive scan of hist -> starts (and cursor copy)
// ---------------------------------------------------------------------------
__global__ void scan1_kernel(int n) {
    __shared__ int s[1024];
    int i = blockIdx.x * 1024 + threadIdx.x;
    int v = (i < n) ? g_hist[i] : 0;
    s[threadIdx.x] = v;
    __syncthreads();
    for (int off = 1; off < 1024; off <<= 1) {
        int t = (threadIdx.x >= off) ? s[threadIdx.x - off] : 0;
        __syncthreads();
        s[threadIdx.x] += t;
        __syncthreads();
    }
    int excl = s[threadIdx.x] - v;
    if (i < n) g_starts[i] = excl;
    if (threadIdx.x == 1023) g_blocksum[blockIdx.x] = s[1023];
}

__global__ void scan2_kernel(int nb) {
    if (threadIdx.x == 0 && blockIdx.x == 0) {
        int run = 0;
        for (int b = 0; b < nb; b++) {
            int t = g_blocksum[b];
            g_blocksum[b] = run;
            run += t;
        }
    }
}

__global__ void scan3_kernel(int n) {
    int i = blockIdx.x * blockDim.x + threadIdx.x;
    if (i < n) {
        int v = g_starts[i] + g_blocksum[i >> 10];
        g_starts[i] = v;
        g_cursor[i] = v;
    }
}

// ---------------------------------------------------------------------------
// K4: reorder edges into src-sorted buckets
// ---------------------------------------------------------------------------
__global__ void reorder_kernel(const int* __restrict__ ei,
                               const float* __restrict__ prob,
                               int n_edges) {
    int e = blockIdx.x * blockDim.x + threadIdx.x;
    if (e >= n_edges) return;
    int src = __ldg(&ei[e]);
    int dst = __ldg(&ei[n_edges + e]);
    float p = __ldg(&prob[e]);
    int pos = atomicAdd(&g_cursor[src], 1);
    g_meta[pos] = make_int2(dst, __float_as_int(p));
}

// ---------------------------------------------------------------------------
// K5: warp-per-node gather-reduce.  NO atomics: each node written once.
//   agg[n] = sum over its edges of prob * hidden[dst]
// 4-way unroll for memory-level parallelism on the 512B row gathers.
// ---------------------------------------------------------------------------
__global__ void aggregate_kernel(const float* __restrict__ hidden,
                                 int n_nodes, int n_edges) {
    int gw   = (blockIdx.x * blockDim.x + threadIdx.x) >> 5;
    int lane = threadIdx.x & 31;
    if (gw >= n_nodes) return;

    int beg = __ldg(&g_starts[gw]);
    int end = (gw + 1 < n_nodes) ? __ldg(&g_starts[gw + 1]) : n_edges;

    float4 acc = make_float4(0.f, 0.f, 0.f, 0.f);
    int e = beg;
    for (; e + 4 <= end; e += 4) {
        int2 m0 = __ldg(&g_meta[e]);
        int2 m1 = __ldg(&g_meta[e + 1]);
        int2 m2 = __ldg(&g_meta[e + 2]);
        int2 m3 = __ldg(&g_meta[e + 3]);
        float4 h0 = __ldg((const float4*)(hidden + (size_t)m0.x * HIDDEN) + lane);
        float4 h1 = __ldg((const float4*)(hidden + (size_t)m1.x * HIDDEN) + lane);
        float4 h2 = __ldg((const float4*)(hidden + (size_t)m2.x * HIDDEN) + lane);
        float4 h3 = __ldg((const float4*)(hidden + (size_t)m3.x * HIDDEN) + lane);
        float p0 = __int_as_float(m0.y), p1 = __int_as_float(m1.y);
        float p2 = __int_as_float(m2.y), p3 = __int_as_float(m3.y);
        acc.x = fmaf(p0, h0.x, acc.x); acc.y = fmaf(p0, h0.y, acc.y);
        acc.z = fmaf(p0, h0.z, acc.z); acc.w = fmaf(p0, h0.w, acc.w);
        acc.x = fmaf(p1, h1.x, acc.x); acc.y = fmaf(p1, h1.y, acc.y);
        acc.z = fmaf(p1, h1.z, acc.z); acc.w = fmaf(p1, h1.w, acc.w);
        acc.x = fmaf(p2, h2.x, acc.x); acc.y = fmaf(p2, h2.y, acc.y);
        acc.z = fmaf(p2, h2.z, acc.z); acc.w = fmaf(p2, h2.w, acc.w);
        acc.x = fmaf(p3, h3.x, acc.x); acc.y = fmaf(p3, h3.y, acc.y);
        acc.z = fmaf(p3, h3.z, acc.z); acc.w = fmaf(p3, h3.w, acc.w);
    }
    for (; e < end; e++) {
        int2 m = __ldg(&g_meta[e]);
        float4 h = __ldg((const float4*)(hidden + (size_t)m.x * HIDDEN) + lane);
        float p = __int_as_float(m.y);
        acc.x = fmaf(p, h.x, acc.x); acc.y = fmaf(p, h.y, acc.y);
        acc.z = fmaf(p, h.z, acc.z); acc.w = fmaf(p, h.w, acc.w);
    }
    ((float4*)(g_agg + (size_t)gw * HIDDEN))[lane] = acc;
}

// ---------------------------------------------------------------------------
// K6: out = agg @ W^T + b.  512 threads, 128-row block tile, 8x4 micro-tile.
// smem: Ws[128*132] (transposed, padded) | As[128*128] | Bs[128]
// ---------------------------------------------------------------------------
#define WPAD 132
#define GEMM_THREADS 512

__global__ __launch_bounds__(GEMM_THREADS, 1)
void gemm_kernel(const float* __restrict__ W,
                 const float* __restrict__ bias,
                 float* __restrict__ out,
                 int n_rows) {
    extern __shared__ float smem[];
    float* Ws = smem;                       // 128 * 132
    float* As = Ws + 128 * WPAD;            // 128 * 128
    float* Bs = As + 128 * 128;             // 128

    // W transposed: Ws[k*WPAD + j] = W[j*128 + k]
    for (int i = threadIdx.x; i < 128 * 128; i += GEMM_THREADS) {
        int j = i >> 7;
        int k = i & 127;
        Ws[k * WPAD + j] = __ldg(&W[i]);
    }
    if (threadIdx.x < 128) Bs[threadIdx.x] = __ldg(&bias[threadIdx.x]);
    __syncthreads();

    int tx = threadIdx.x & 31;   // cols [4*tx, 4*tx+3]
    int ty = threadIdx.x >> 5;   // rows ty + 16*r, r=0..7

    int n_tiles = (n_rows + 127) >> 7;

    for (int tile = blockIdx.x; tile < n_tiles; tile += gridDim.x) {
        int row0 = tile << 7;

        // Stage agg tile [128 x 128] into smem (float4, zero-pad tail rows)
        {
            const float4* src = (const float4*)(g_agg + (size_t)row0 * HIDDEN);
            float4* dstp = (float4*)As;
            for (int i = threadIdx.x; i < 128 * 32; i += GEMM_THREADS) {
                int r = i >> 5;
                dstp[i] = (row0 + r < n_rows) ? __ldg(&src[i])
                                              : make_float4(0.f, 0.f, 0.f, 0.f);
            }
        }
        __syncthreads();

        float4 acc[8];
#pragma unroll
        for (int r = 0; r < 8; r++) acc[r] = make_float4(0.f, 0.f, 0.f, 0.f);

#pragma unroll 4
        for (int k = 0; k < 128; k++) {
            float4 w = *(const float4*)&Ws[k * WPAD + tx * 4];  // conflict-free
#pragma unroll
            for (int r = 0; r < 8; r++) {
                float a = As[(ty + (r << 4)) * 128 + k];         // broadcast
                acc[r].x = fmaf(a, w.x, acc[r].x);
                acc[r].y = fmaf(a, w.y, acc[r].y);
                acc[r].z = fmaf(a, w.z, acc[r].z);
                acc[r].w = fmaf(a, w.w, acc[r].w);
            }
        }

        float4 bv = *(const float4*)&Bs[tx * 4];
#pragma unroll
        for (int r = 0; r < 8; r++) {
            int row = row0 + ty + (r << 4);
            if (row < n_rows) {
                float4 o = make_float4(acc[r].x + bv.x, acc[r].y + bv.y,
                                       acc[r].z + bv.z, acc[r].w + bv.w);
                *(float4*)&out[(size_t)row * HIDDEN + tx * 4] = o;
            }
        }
        __syncthreads();
    }
}

// ---------------------------------------------------------------------------
// Launch
// Inputs: probabilities [E], hidden [N,128], edge_index [2,E],
//         lin_w [128,128], lin_b [128].  Output: [N,128] fp32.
// ---------------------------------------------------------------------------
extern "C" void kernel_launch(void* const* d_in, const int* in_sizes, int n_in,
                              void* d_out, int out_size) {
    const float* prob   = (const float*)d_in[0];
    const float* hidden = (const float*)d_in[1];
    const int*   ei     = (const int*)d_in[2];
    const float* lin_w  = (const float*)d_in[3];
    const float* lin_b  = (const float*)d_in[4];
    float* out = (float*)d_out;

    int n_edges = in_sizes[0];
    int n_nodes = in_sizes[1] / HIDDEN;

    // --- counting sort by src ---
    {
        int blocks = (n_nodes + 255) / 256;
        zero_hist_kernel<<<blocks, 256>>>(n_nodes);
    }
    {
        int blocks = (n_edges + 255) / 256;
        hist_kernel<<<blocks, 256>>>(ei, n_edges);
    }
    {
        int nb = (n_nodes + 1023) / 1024;
        scan1_kernel<<<nb, 1024>>>(n_nodes);
        scan2_kernel<<<1, 32>>>(nb);
        int blocks = (n_nodes + 255) / 256;
        scan3_kernel<<<blocks, 256>>>(n_nodes);
    }
    {
        int blocks = (n_edges + 255) / 256;
        reorder_kernel<<<blocks, 256>>>(ei, prob, n_edges);
    }

    // --- warp-per-node gather-reduce (no atomics) ---
    {
        long long threads = (long long)n_nodes * 32;
        int blocks = (int)((threads + 255) / 256);
        aggregate_kernel<<<blocks, 256>>>(hidden, n_nodes, n_edges);
    }

    // --- linear layer ---
    {
        int smem_bytes = (128 * WPAD + 128 * 128 + 128) * sizeof(float);
        cudaFuncSetAttribute(gemm_kernel,
                             cudaFuncAttributeMaxDynamicSharedMemorySize,
                             smem_bytes);
        int n_tiles = (n_nodes + 127) >> 7;
        int grid = n_tiles < 148 ? n_tiles : 148;
        gemm_kernel<<<grid, GEMM_THREADS, smem_bytes>>>(lin_w, lin_b, out, n_nodes);
    }
}

// round 17
// speedup vs baseline: 1.7955x; 1.0399x over previous
#include <cuda_runtime.h>
#include <cuda_bf16.h>
#include <cstdint>

#define N_NODES_MAX 100000
#define N_EDGES_MAX 1600000
#define HIDDEN 128

// Scratch (allocation-free rule: static __device__ arrays).
__device__ float g_h2[(size_t)N_NODES_MAX * HIDDEN];       // hidden @ W^T  (51.2 MB)
__device__ int2  g_meta[N_EDGES_MAX];                      // src-sorted (dst, prob-bits)
__device__ int   g_hist[N_NODES_MAX];
__device__ int   g_starts[N_NODES_MAX];
__device__ int   g_cursor[N_NODES_MAX];
__device__ int   g_blocksum[256];
__device__ __nv_bfloat16 g_w_hi[HIDDEN * HIDDEN];          // W split to bf16 hi/lo
__device__ __nv_bfloat16 g_w_lo[HIDDEN * HIDDEN];

// ===========================================================================
// PTX helpers (feature-neutral: ldmatrix + mma.sync, NO tcgen05)
// ===========================================================================
__device__ __forceinline__ uint32_t smem_u32(const void* p) {
    uint32_t a;
    asm("{ .reg .u64 t; cvta.to.shared.u64 t, %1; cvt.u32.u64 %0, t; }"
        : "=r"(a) : "l"(p));
    return a;
}
__device__ __forceinline__ void ldsm_x4(uint32_t* r, uint32_t addr) {
    asm volatile("ldmatrix.sync.aligned.m8n8.x4.shared.b16 {%0,%1,%2,%3}, [%4];"
                 : "=r"(r[0]), "=r"(r[1]), "=r"(r[2]), "=r"(r[3]) : "r"(addr));
}
// NON-transposed x2: W is [n][k] row-major == B col-major (K x N) for
// mma row.col, so each lane addresses an n-row and gets 2 consecutive k.
__device__ __forceinline__ void ldsm_x2(uint32_t* r, uint32_t addr) {
    asm volatile("ldmatrix.sync.aligned.m8n8.x2.shared.b16 {%0,%1}, [%2];"
                 : "=r"(r[0]), "=r"(r[1]) : "r"(addr));
}
__device__ __forceinline__ void mma16816(float* d, const uint32_t* a,
                                         const uint32_t* b) {
    asm volatile(
        "mma.sync.aligned.m16n8k16.row.col.f32.bf16.bf16.f32 "
        "{%0,%1,%2,%3}, {%4,%5,%6,%7}, {%8,%9}, {%0,%1,%2,%3};"
        : "+f"(d[0]), "+f"(d[1]), "+f"(d[2]), "+f"(d[3])
        : "r"(a[0]), "r"(a[1]), "r"(a[2]), "r"(a[3]), "r"(b[0]), "r"(b[1]));
}

// ===========================================================================
// Counting sort kernels (src-bucketed edges)
// ===========================================================================
__global__ void zero_hist_kernel(int n) {
    int i = blockIdx.x * blockDim.x + threadIdx.x;
    if (i < n) g_hist[i] = 0;
}

__global__ void hist_kernel(const int* __restrict__ ei, int n_edges) {
    int e = blockIdx.x * blockDim.x + threadIdx.x;
    if (e < n_edges) atomicAdd(&g_hist[__ldg(&ei[e])], 1);
}

__global__ void scan1_kernel(int n) {
    __shared__ int s[1024];
    int i = blockIdx.x * 1024 + threadIdx.x;
    int v = (i < n) ? g_hist[i] : 0;
    s[threadIdx.x] = v;
    __syncthreads();
    for (int off = 1; off < 1024; off <<= 1) {
        int t = (threadIdx.x >= off) ? s[threadIdx.x - off] : 0;
        __syncthreads();
        s[threadIdx.x] += t;
        __syncthreads();
    }
    int excl = s[threadIdx.x] - v;
    if (i < n) g_starts[i] = excl;
    if (threadIdx.x == 1023) g_blocksum[blockIdx.x] = s[1023];
}

// Parallel exclusive scan of block sums (nb <= 128).
__global__ void scan2_kernel(int nb) {
    __shared__ int s[128];
    int v = (threadIdx.x < nb) ? g_blocksum[threadIdx.x] : 0;
    s[threadIdx.x] = v;
    __syncthreads();
    for (int off = 1; off < 128; off <<= 1) {
        int t = (threadIdx.x >= off) ? s[threadIdx.x - off] : 0;
        __syncthreads();
        s[threadIdx.x] += t;
        __syncthreads();
    }
    if (threadIdx.x < nb) g_blocksum[threadIdx.x] = s[threadIdx.x] - v;
}

__global__ void scan3_kernel(int n) {
    int i = blockIdx.x * blockDim.x + threadIdx.x;
    if (i < n) {
        int v = g_starts[i] + g_blocksum[i >> 10];
        g_starts[i] = v;
        g_cursor[i] = v;
    }
}

__global__ void reorder_kernel(const int* __restrict__ ei,
                               const float* __restrict__ prob,
                               int n_edges) {
    int e = blockIdx.x * blockDim.x + threadIdx.x;
    if (e >= n_edges) return;
    int src = __ldg(&ei[e]);
    int dst = __ldg(&ei[n_edges + e]);
    float p = __ldg(&prob[e]);
    int pos = atomicAdd(&g_cursor[src], 1);
    g_meta[pos] = make_int2(dst, __float_as_int(p));
}

// ===========================================================================
// W split: one-time fp32 -> bf16 hi/lo (row-major [out][in] = [n][k])
// ===========================================================================
__global__ void wconv_kernel(const float* __restrict__ W) {
    int i = blockIdx.x * blockDim.x + threadIdx.x;
    if (i < HIDDEN * HIDDEN) {
        float v = __ldg(&W[i]);
        __nv_bfloat16 hi = __float2bfloat16(v);
        g_w_hi[i] = hi;
        g_w_lo[i] = __float2bfloat16(v - __bfloat162float(hi));
    }
}

// ===========================================================================
// GEMM: g_h2 = hidden @ W^T via mma.sync m16n8k16 bf16x3 split precision.
// One CTA per 128-row tile; 256 threads = 8 warps, warp w owns rows w*16..+15.
// smem padded bf16 [128][136] (row stride 272B = 17 x 16B, odd -> ldmatrix
// conflict-free).
// ===========================================================================
#define APAD 136
#define AH_OFF 0
#define AL_OFF (128 * APAD * 2)
#define WH_OFF (2 * 128 * APAD * 2)
#define WL_OFF (3 * 128 * APAD * 2)
#define GSMEM_SZ (4 * 128 * APAD * 2)

__global__ __launch_bounds__(256, 1)
void gemm_mma_kernel(const float* __restrict__ hidden, int n_rows) {
    extern __shared__ char smem[];
    uint32_t sbase = smem_u32(smem);
    int tid  = threadIdx.x;
    int wid  = tid >> 5;
    int lane = tid & 31;
    int row0 = blockIdx.x << 7;

    // --- copy pre-split W into padded smem (uint4 = 8 bf16) ---
    {
        const uint4* wh = (const uint4*)g_w_hi;
        const uint4* wl = (const uint4*)g_w_lo;
        for (int i = tid; i < 128 * 16; i += 256) {
            int r  = i >> 4;
            int c8 = (i & 15) << 3;
            *(uint4*)(smem + WH_OFF + (r * APAD + c8) * 2) = __ldg(&wh[i]);
            *(uint4*)(smem + WL_OFF + (r * APAD + c8) * 2) = __ldg(&wl[i]);
        }
    }

    // --- convert A tile fp32 -> bf16 hi/lo into padded smem ---
    for (int i = tid; i < 128 * 32; i += 256) {
        int r  = i >> 5;
        int c4 = (i & 31) << 2;
        float4 v = (row0 + r < n_rows)
            ? __ldg((const float4*)(hidden + (size_t)(row0 + r) * HIDDEN) + (i & 31))
            : make_float4(0.f, 0.f, 0.f, 0.f);
        uint32_t h0 = (uint32_t)__bfloat16_as_ushort(__float2bfloat16(v.x));
        uint32_t h1 = (uint32_t)__bfloat16_as_ushort(__float2bfloat16(v.y));
        uint32_t h2 = (uint32_t)__bfloat16_as_ushort(__float2bfloat16(v.z));
        uint32_t h3 = (uint32_t)__bfloat16_as_ushort(__float2bfloat16(v.w));
        float l0 = v.x - __uint_as_float(h0 << 16);
        float l1 = v.y - __uint_as_float(h1 << 16);
        float l2 = v.z - __uint_as_float(h2 << 16);
        float l3 = v.w - __uint_as_float(h3 << 16);
        uint32_t g0 = (uint32_t)__bfloat16_as_ushort(__float2bfloat16(l0));
        uint32_t g1 = (uint32_t)__bfloat16_as_ushort(__float2bfloat16(l1));
        uint32_t g2 = (uint32_t)__bfloat16_as_ushort(__float2bfloat16(l2));
        uint32_t g3 = (uint32_t)__bfloat16_as_ushort(__float2bfloat16(l3));
        uint32_t off = (uint32_t)(r * APAD + c4) * 2;
        *(uint2*)(smem + AH_OFF + off) = make_uint2(h0 | (h1 << 16), h2 | (h3 << 16));
        *(uint2*)(smem + AL_OFF + off) = make_uint2(g0 | (g1 << 16), g2 | (g3 << 16));
    }
    __syncthreads();

    // --- MMA mainloop: D = A_hi*W_hi^T + A_hi*W_lo^T + A_lo*W_hi^T ---
    float d[16][4];
#pragma unroll
    for (int nt = 0; nt < 16; nt++) {
        d[nt][0] = 0.f; d[nt][1] = 0.f; d[nt][2] = 0.f; d[nt][3] = 0.f;
    }

    // A ldmatrix addressing (x4): lanes 0-15 -> rows (k-half 0),
    // lanes 16-31 -> rows (k-half 8).
    uint32_t a_row   = (uint32_t)(wid * 16 + (lane & 15));
    uint32_t a_khalf = (uint32_t)(lane >> 4) * 8;
    // B ldmatrix addressing (x2, non-trans): lanes 0-7 -> n-rows k-half 0,
    // lanes 8-15 -> n-rows k-half 8.
    uint32_t b_nrow  = (uint32_t)(lane & 7);
    uint32_t b_khalf = (uint32_t)((lane >> 3) & 1) * 8;

#pragma unroll
    for (int kk = 0; kk < 8; kk++) {
        uint32_t a_off = (a_row * APAD + kk * 16 + a_khalf) * 2;
        uint32_t ah[4], al[4];
        ldsm_x4(ah, sbase + AH_OFF + a_off);
        ldsm_x4(al, sbase + AL_OFF + a_off);
#pragma unroll
        for (int nt = 0; nt < 16; nt++) {
            uint32_t b_off = ((nt * 8 + b_nrow) * APAD + kk * 16 + b_khalf) * 2;
            uint32_t bh[2], bl[2];
            ldsm_x2(bh, sbase + WH_OFF + b_off);
            ldsm_x2(bl, sbase + WL_OFF + b_off);
            mma16816(d[nt], ah, bh);
            mma16816(d[nt], ah, bl);
            mma16816(d[nt], al, bh);
        }
    }

    // --- store D: thread (lane) covers rows (lane>>2) and (lane>>2)+8 ---
    int r_lo = row0 + wid * 16 + (lane >> 2);
    int col0 = (lane & 3) * 2;
    bool ok0 = r_lo < n_rows;
    bool ok1 = r_lo + 8 < n_rows;
#pragma unroll
    for (int nt = 0; nt < 16; nt++) {
        int c = nt * 8 + col0;
        if (ok0) *(float2*)&g_h2[(size_t)r_lo * HIDDEN + c] =
                     make_float2(d[nt][0], d[nt][1]);
        if (ok1) *(float2*)&g_h2[(size_t)(r_lo + 8) * HIDDEN + c] =
                     make_float2(d[nt][2], d[nt][3]);
    }
}

// ===========================================================================
// Aggregate: out[n] = bias + sum_{e in bucket(n)} p_e * g_h2[dst_e]
// Warp per node, no atomics, bias folded in.
// ===========================================================================
__global__ void aggregate_kernel(const float* __restrict__ bias,
                                 float* __restrict__ out,
                                 int n_nodes, int n_edges) {
    int gw   = (blockIdx.x * blockDim.x + threadIdx.x) >> 5;
    int lane = threadIdx.x & 31;
    if (gw >= n_nodes) return;

    int beg = __ldg(&g_starts[gw]);
    int end = (gw + 1 < n_nodes) ? __ldg(&g_starts[gw + 1]) : n_edges;

    float4 acc = __ldg((const float4*)bias + lane);
    int e = beg;
    for (; e + 4 <= end; e += 4) {
        int2 m0 = __ldg(&g_meta[e]);
        int2 m1 = __ldg(&g_meta[e + 1]);
        int2 m2 = __ldg(&g_meta[e + 2]);
        int2 m3 = __ldg(&g_meta[e + 3]);
        float4 h0 = __ldg((const float4*)(g_h2 + (size_t)m0.x * HIDDEN) + lane);
        float4 h1 = __ldg((const float4*)(g_h2 + (size_t)m1.x * HIDDEN) + lane);
        float4 h2 = __ldg((const float4*)(g_h2 + (size_t)m2.x * HIDDEN) + lane);
        float4 h3 = __ldg((const float4*)(g_h2 + (size_t)m3.x * HIDDEN) + lane);
        float p0 = __int_as_float(m0.y), p1 = __int_as_float(m1.y);
        float p2 = __int_as_float(m2.y), p3 = __int_as_float(m3.y);
        acc.x = fmaf(p0, h0.x, acc.x); acc.y = fmaf(p0, h0.y, acc.y);
        acc.z = fmaf(p0, h0.z, acc.z); acc.w = fmaf(p0, h0.w, acc.w);
        acc.x = fmaf(p1, h1.x, acc.x); acc.y = fmaf(p1, h1.y, acc.y);
        acc.z = fmaf(p1, h1.z, acc.z); acc.w = fmaf(p1, h1.w, acc.w);
        acc.x = fmaf(p2, h2.x, acc.x); acc.y = fmaf(p2, h2.y, acc.y);
        acc.z = fmaf(p2, h2.z, acc.z); acc.w = fmaf(p2, h2.w, acc.w);
        acc.x = fmaf(p3, h3.x, acc.x); acc.y = fmaf(p3, h3.y, acc.y);
        acc.z = fmaf(p3, h3.z, acc.z); acc.w = fmaf(p3, h3.w, acc.w);
    }
    for (; e < end; e++) {
        int2 m = __ldg(&g_meta[e]);
        float4 h = __ldg((const float4*)(g_h2 + (size_t)m.x * HIDDEN) + lane);
        float p = __int_as_float(m.y);
        acc.x = fmaf(p, h.x, acc.x); acc.y = fmaf(p, h.y, acc.y);
        acc.z = fmaf(p, h.z, acc.z); acc.w = fmaf(p, h.w, acc.w);
    }
    ((float4*)(out + (size_t)gw * HIDDEN))[lane] = acc;
}

// ===========================================================================
// Launch
// Inputs: probabilities [E], hidden [N,128], edge_index [2,E],
//         lin_w [128,128], lin_b [128].  Output: [N,128] fp32.
// ===========================================================================
extern "C" void kernel_launch(void* const* d_in, const int* in_sizes, int n_in,
                              void* d_out, int out_size) {
    const float* prob   = (const float*)d_in[0];
    const float* hidden = (const float*)d_in[1];
    const int*   ei     = (const int*)d_in[2];
    const float* lin_w  = (const float*)d_in[3];
    const float* lin_b  = (const float*)d_in[4];
    float* out = (float*)d_out;

    int n_edges = in_sizes[0];
    int n_nodes = in_sizes[1] / HIDDEN;

    // --- W split + GEMM: g_h2 = hidden @ W^T ---
    wconv_kernel<<<(HIDDEN * HIDDEN + 255) / 256, 256>>>(lin_w);
    {
        cudaFuncSetAttribute(gemm_mma_kernel,
                             cudaFuncAttributeMaxDynamicSharedMemorySize,
                             GSMEM_SZ);
        int n_tiles = (n_nodes + 127) >> 7;
        gemm_mma_kernel<<<n_tiles, 256, GSMEM_SZ>>>(hidden, n_nodes);
    }

    // --- counting sort by src ---
    {
        int blocks = (n_nodes + 255) / 256;
        zero_hist_kernel<<<blocks, 256>>>(n_nodes);
    }
    {
        int blocks = (n_edges + 255) / 256;
        hist_kernel<<<blocks, 256>>>(ei, n_edges);
    }
    {
        int nb = (n_nodes + 1023) / 1024;
        scan1_kernel<<<nb, 1024>>>(n_nodes);
        scan2_kernel<<<1, 128>>>(nb);
        int blocks = (n_nodes + 255) / 256;
        scan3_kernel<<<blocks, 256>>>(n_nodes);
    }
    {
        int blocks = (n_edges + 255) / 256;
        reorder_kernel<<<blocks, 256>>>(ei, prob, n_edges);
    }

    // --- warp-per-node gather-reduce over g_h2, bias folded in ---
    {
        long long threads = (long long)n_nodes * 32;
        int blocks = (int)((threads + 255) / 256);
        aggregate_kernel<<<blocks, 256>>>(lin_b, out, n_nodes, n_edges);
    }
}